// round 2
// baseline (speedup 1.0000x reference)
#include <cuda_runtime.h>
#include <math.h>

// Problem constants
#define BB 2
#define SS 513
#define HH 512
#define NHH 8
#define DD 64
#define SCALE 0.125f   // 1/sqrt(64)

// Scratch (device globals: no allocation allowed)
__device__ float g_Q[BB*SS*HH];
__device__ float g_K[BB*SS*HH];
__device__ float g_V[BB*SS*HH];
__device__ float g_X[BB*SS*HH];
__device__ float g_Vsum[BB*NHH*DD];

// Token index for the i-th row of mask-group f (within one batch).
// f=0,1,2 -> positions 0,1,2 of each 9-long statement (57 each)
// f=3 -> positions 3,5,7 (171); f=4 -> positions 4,6,8 (171)
__device__ __forceinline__ int row_to_token(int f, int i) {
    if (f < 3) return 9*i + f;
    int s = i / 3, j = i % 3;
    return 9*s + ((f == 3) ? (3 + 2*j) : (4 + 2*j));
}

// ---------------------------------------------------------------------------
// Kernel 1: grouped projection GEMM.
// For each (tensor in {q,k,v}, f in 0..4): Y[rows_f] = X[rows_f] @ W_f^T + sum_f b_f
// blockIdx.z = tensor*5 + f; 64x64 tile, BK=16, 256 threads, 4x4 per thread.
// ---------------------------------------------------------------------------
__global__ void prep_gemm(const float* __restrict__ xq, const float* __restrict__ xk,
                          const float* __restrict__ xv,
                          const float* __restrict__ Wq, const float* __restrict__ bq,
                          const float* __restrict__ Wk, const float* __restrict__ bk,
                          const float* __restrict__ Wv, const float* __restrict__ bv) {
    const int g = blockIdx.z;
    const int tensor = g / 5, f = g % 5;
    const int rpb = (f < 3) ? 57 : 171;       // rows per batch in this group
    const int M = 2 * rpb;
    const int m0 = blockIdx.x * 64;
    if (m0 >= M) return;
    const int n0 = blockIdx.y * 64;

    const float* X    = (tensor == 0) ? xq : (tensor == 1) ? xk : xv;
    const float* W    = ((tensor == 0) ? Wq : (tensor == 1) ? Wk : Wv) + f*HH*HH;
    const float* bias = (tensor == 0) ? bq : (tensor == 1) ? bk : bv;
    float* Y          = (tensor == 0) ? g_Q : (tensor == 1) ? g_K : g_V;

    __shared__ float As[64][17];
    __shared__ float Bs[16][68];
    __shared__ int rowoff[64];

    const int tid = threadIdx.x;
    if (tid < 64) {
        int r = m0 + tid;
        if (r < M) {
            int b = r / rpb, i = r % rpb;
            rowoff[tid] = (b*SS + row_to_token(f, i)) * HH;
        } else rowoff[tid] = -1;
    }
    __syncthreads();

    float acc[4][4] = {};
    const int tr = (tid / 16) * 4;
    const int tc = (tid % 16) * 4;

    for (int kk = 0; kk < HH; kk += 16) {
        #pragma unroll
        for (int j = 0; j < 4; j++) {
            int idx = tid*4 + j;
            int r = idx >> 4, c = idx & 15;
            int off = rowoff[r];
            As[r][c] = (off >= 0) ? X[off + kk + c] : 0.f;
        }
        #pragma unroll
        for (int j = 0; j < 4; j++) {
            int idx = tid + j*256;
            int n = idx >> 4, c = idx & 15;
            Bs[c][n] = W[(n0 + n)*HH + kk + c];
        }
        __syncthreads();
        #pragma unroll
        for (int p = 0; p < 16; p++) {
            float a0 = As[tr+0][p], a1 = As[tr+1][p], a2 = As[tr+2][p], a3 = As[tr+3][p];
            float b0 = Bs[p][tc+0], b1 = Bs[p][tc+1], b2 = Bs[p][tc+2], b3 = Bs[p][tc+3];
            acc[0][0] += a0*b0; acc[0][1] += a0*b1; acc[0][2] += a0*b2; acc[0][3] += a0*b3;
            acc[1][0] += a1*b0; acc[1][1] += a1*b1; acc[1][2] += a1*b2; acc[1][3] += a1*b3;
            acc[2][0] += a2*b0; acc[2][1] += a2*b1; acc[2][2] += a2*b2; acc[2][3] += a2*b3;
            acc[3][0] += a3*b0; acc[3][1] += a3*b1; acc[3][2] += a3*b2; acc[3][3] += a3*b3;
        }
        __syncthreads();
    }

    float bsum[4];
    #pragma unroll
    for (int j = 0; j < 4; j++) {
        int n = n0 + tc + j;
        bsum[j] = bias[n] + bias[HH+n] + bias[2*HH+n] + bias[3*HH+n] + bias[4*HH+n];
    }
    #pragma unroll
    for (int i = 0; i < 4; i++) {
        int off = rowoff[tr + i];
        if (off < 0) continue;
        #pragma unroll
        for (int j = 0; j < 4; j++)
            Y[off + n0 + tc + j] = acc[i][j] + bsum[j];
    }
}

// ---------------------------------------------------------------------------
// Kernel 2: per-(b,head) column sums of V  (needed by the fully-masked path)
// ---------------------------------------------------------------------------
__global__ void vsum_kernel() {
    const int b = blockIdx.x / NHH, h = blockIdx.x % NHH;
    const int d = threadIdx.x;
    float a = 0.f;
    for (int k = 0; k < SS; k++) a += g_V[(b*SS + k)*HH + h*DD + d];
    g_Vsum[(b*NHH + h)*DD + d] = a;
}

// ---------------------------------------------------------------------------
// Kernel 3: sparse attention rows (q >= 3): at most 5 kept columns.
// score(q,k,h) = (q_h + eq[k,q]) . (k_h + ek[q,k])   [exact factorization]
// One block per (b,q); 8 warps = 8 heads; lane handles 2 of 64 dims.
// Fully-masked rows reproduce reference softmax(-1e5*ones) = uniform 1/S.
// ---------------------------------------------------------------------------
__global__ void attn_sparse(const int* __restrict__ graph,
                            const float* __restrict__ EK,
                            const float* __restrict__ EV,
                            const float* __restrict__ EQ) {
    const int idx = blockIdx.x;
    const int b = idx / (SS - 3);
    const int q = 3 + idx % (SS - 3);
    const int g2 = 3 + ((q - 3) >> 1) * 2;   // kept pair start
    const int tid = threadIdx.x;

    __shared__ float s_eq[5][64], s_ek[5][64], s_ev[5][64];
    __shared__ int s_g[5];
    __shared__ float s_red[4][64];

    if (tid < 5) {
        int k = (tid < 3) ? tid : g2 + tid - 3;
        s_g[tid] = (graph[(b*SS + q)*SS + k] != 0);
    }
    for (int i = tid; i < 5*64; i += 256) {
        int j = i >> 6, d = i & 63;
        int k = (j < 3) ? j : g2 + j - 3;
        s_eq[j][d] = EQ[((b*SS + k)*SS + q)*DD + d];
        s_ek[j][d] = EK[((b*SS + q)*SS + k)*DD + d];
        s_ev[j][d] = EV[((b*SS + q)*SS + k)*DD + d];
    }
    __syncthreads();

    const int any = s_g[0] | s_g[1] | s_g[2] | s_g[3] | s_g[4];
    const int h = tid >> 5, lane = tid & 31;
    const int d2 = lane * 2;
    const int obase = (b*SS + q)*HH + h*DD + d2;

    if (any) {
        float2 qh = *(const float2*)(g_Q + obase);
        float sc[5];
        #pragma unroll
        for (int j = 0; j < 5; j++) {
            int k = (j < 3) ? j : g2 + j - 3;
            float2 kv = *(const float2*)(g_K + (b*SS + k)*HH + h*DD + d2);
            float s = (qh.x + s_eq[j][d2  ]) * (kv.x + s_ek[j][d2  ])
                    + (qh.y + s_eq[j][d2+1]) * (kv.y + s_ek[j][d2+1]);
            #pragma unroll
            for (int o = 16; o; o >>= 1) s += __shfl_xor_sync(0xffffffffu, s, o);
            sc[j] = s * SCALE;
        }
        float mx = -1e30f;
        #pragma unroll
        for (int j = 0; j < 5; j++) if (s_g[j]) mx = fmaxf(mx, sc[j]);
        float w[5]; float den = 0.f;
        #pragma unroll
        for (int j = 0; j < 5; j++) { w[j] = s_g[j] ? expf(sc[j] - mx) : 0.f; den += w[j]; }
        const float inv = 1.f / den;
        float ax = 0.f, ay = 0.f;
        #pragma unroll
        for (int j = 0; j < 5; j++) {
            float wj = w[j] * inv;
            int k = (j < 3) ? j : g2 + j - 3;
            float2 vv = *(const float2*)(g_V + (b*SS + k)*HH + h*DD + d2);
            ax += wj * (vv.x + s_ev[j][d2  ]);
            ay += wj * (vv.y + s_ev[j][d2+1]);
        }
        g_X[obase] = ax; g_X[obase + 1] = ay;
    } else {
        // reference: softmax of all -100000 -> uniform 1/S over ALL columns
        const int grp = tid >> 6, dd = tid & 63;
        const float* evrow = EV + (b*SS + q)*SS*DD;
        float a = 0.f;
        for (int k = grp; k < SS; k += 4) a += evrow[k*DD + dd];
        s_red[grp][dd] = a;
        __syncthreads();
        float e0 = s_red[0][d2  ] + s_red[1][d2  ] + s_red[2][d2  ] + s_red[3][d2  ];
        float e1 = s_red[0][d2+1] + s_red[1][d2+1] + s_red[2][d2+1] + s_red[3][d2+1];
        float v0 = g_Vsum[(b*NHH + h)*DD + d2];
        float v1 = g_Vsum[(b*NHH + h)*DD + d2 + 1];
        const float u = 1.f / (float)SS;
        g_X[obase]     = (v0 + e0) * u;
        g_X[obase + 1] = (v1 + e1) * u;
    }
}

// ---------------------------------------------------------------------------
// Kernel 4: dense attention rows (q in {0,1,2}): full 513-column softmax,
// masked only by graph. One block per (b,q); scores staged in smem.
// ---------------------------------------------------------------------------
__global__ void attn_dense(const int* __restrict__ graph,
                           const float* __restrict__ EK,
                           const float* __restrict__ EV,
                           const float* __restrict__ EQ) {
    const int b = blockIdx.x / 3;
    const int q = blockIdx.x % 3;
    const int tid = threadIdx.x;
    const int w = tid >> 5, lane = tid & 31, d2 = lane * 2;

    __shared__ float s_q[HH];
    __shared__ float s_s[NHH][SS + 3];
    __shared__ int s_m[SS];

    for (int i = tid; i < HH; i += 256) s_q[i] = g_Q[(b*SS + q)*HH + i];
    for (int k = tid; k < SS; k += 256) s_m[k] = (graph[(b*SS + q)*SS + k] != 0);
    __syncthreads();

    // scores: warp w handles columns k = w, w+8, ...
    for (int k = w; k < SS; k += 8) {
        float eqx = EQ[((b*SS + k)*SS + q)*DD + d2];
        float eqy = EQ[((b*SS + k)*SS + q)*DD + d2 + 1];
        float ekx = EK[((b*SS + q)*SS + k)*DD + d2];
        float eky = EK[((b*SS + q)*SS + k)*DD + d2 + 1];
        #pragma unroll
        for (int h = 0; h < NHH; h++) {
            float2 kv = *(const float2*)(g_K + (b*SS + k)*HH + h*DD + d2);
            float s = (s_q[h*DD + d2] + eqx) * (kv.x + ekx)
                    + (s_q[h*DD + d2 + 1] + eqy) * (kv.y + eky);
            #pragma unroll
            for (int o = 16; o; o >>= 1) s += __shfl_xor_sync(0xffffffffu, s, o);
            if (lane == 0) s_s[h][k] = s * SCALE;
        }
    }
    __syncthreads();

    // masked softmax, warp w = head w
    {
        const int h = w;
        float mx = -1e30f;
        for (int k = lane; k < SS; k += 32) if (s_m[k]) mx = fmaxf(mx, s_s[h][k]);
        #pragma unroll
        for (int o = 16; o; o >>= 1) mx = fmaxf(mx, __shfl_xor_sync(0xffffffffu, mx, o));
        float den = 0.f;
        for (int k = lane; k < SS; k += 32) {
            float e = s_m[k] ? expf(s_s[h][k] - mx) : 0.f;
            s_s[h][k] = e; den += e;
        }
        #pragma unroll
        for (int o = 16; o; o >>= 1) den += __shfl_xor_sync(0xffffffffu, den, o);
        if (den > 0.f) {
            float inv = 1.f / den;
            for (int k = lane; k < SS; k += 32) s_s[h][k] *= inv;
        } else {
            float u = 1.f / (float)SS;       // fully masked -> uniform over all
            for (int k = lane; k < SS; k += 32) s_s[h][k] = u;
        }
    }
    __syncthreads();

    // weighted sum of (v + edge_value)
    {
        const int h = w;
        float ax = 0.f, ay = 0.f;
        for (int k = 0; k < SS; k++) {
            float pk = s_s[h][k];
            if (pk != 0.f) {
                float2 vv = *(const float2*)(g_V + (b*SS + k)*HH + h*DD + d2);
                float evx = EV[((b*SS + q)*SS + k)*DD + d2];
                float evy = EV[((b*SS + q)*SS + k)*DD + d2 + 1];
                ax += pk * (vv.x + evx);
                ay += pk * (vv.y + evy);
            }
        }
        int ob = (b*SS + q)*HH + h*DD + d2;
        g_X[ob] = ax; g_X[ob + 1] = ay;
    }
}

// ---------------------------------------------------------------------------
// Kernel 5: output projection  out = X @ Wo^T + bo   (M=1026, N=K=512)
// ---------------------------------------------------------------------------
__global__ void out_gemm(const float* __restrict__ Wo, const float* __restrict__ bo,
                         float* __restrict__ out) {
    const int M = BB * SS;
    const int m0 = blockIdx.x * 64;
    const int n0 = blockIdx.y * 64;

    __shared__ float As[64][17];
    __shared__ float Bs[16][68];

    const int tid = threadIdx.x;
    float acc[4][4] = {};
    const int tr = (tid / 16) * 4;
    const int tc = (tid % 16) * 4;

    for (int kk = 0; kk < HH; kk += 16) {
        #pragma unroll
        for (int j = 0; j < 4; j++) {
            int idx = tid*4 + j;
            int r = idx >> 4, c = idx & 15;
            int row = m0 + r;
            As[r][c] = (row < M) ? g_X[row*HH + kk + c] : 0.f;
        }
        #pragma unroll
        for (int j = 0; j < 4; j++) {
            int idx = tid + j*256;
            int n = idx >> 4, c = idx & 15;
            Bs[c][n] = Wo[(n0 + n)*HH + kk + c];
        }
        __syncthreads();
        #pragma unroll
        for (int p = 0; p < 16; p++) {
            float a0 = As[tr+0][p], a1 = As[tr+1][p], a2 = As[tr+2][p], a3 = As[tr+3][p];
            float b0 = Bs[p][tc+0], b1 = Bs[p][tc+1], b2 = Bs[p][tc+2], b3 = Bs[p][tc+3];
            acc[0][0] += a0*b0; acc[0][1] += a0*b1; acc[0][2] += a0*b2; acc[0][3] += a0*b3;
            acc[1][0] += a1*b0; acc[1][1] += a1*b1; acc[1][2] += a1*b2; acc[1][3] += a1*b3;
            acc[2][0] += a2*b0; acc[2][1] += a2*b1; acc[2][2] += a2*b2; acc[2][3] += a2*b3;
            acc[3][0] += a3*b0; acc[3][1] += a3*b1; acc[3][2] += a3*b2; acc[3][3] += a3*b3;
        }
        __syncthreads();
    }
    #pragma unroll
    for (int i = 0; i < 4; i++) {
        int row = m0 + tr + i;
        if (row >= M) continue;
        #pragma unroll
        for (int j = 0; j < 4; j++)
            out[row*HH + n0 + tc + j] = acc[i][j] + bo[n0 + tc + j];
    }
}

// ---------------------------------------------------------------------------
extern "C" void kernel_launch(void* const* d_in, const int* in_sizes, int n_in,
                              void* d_out, int out_size) {
    (void)in_sizes; (void)n_in; (void)out_size;
    const float* q_in  = (const float*)d_in[0];
    const float* k_in  = (const float*)d_in[1];
    const float* v_in  = (const float*)d_in[2];
    const int*   graph = (const int*)  d_in[3];   // bool -> 32-bit nonzero test (i32 or f32 safe)
    const float* ek    = (const float*)d_in[4];
    const float* ev    = (const float*)d_in[5];
    const float* eq    = (const float*)d_in[6];
    const float* Wq    = (const float*)d_in[7];
    const float* bq    = (const float*)d_in[8];
    const float* Wk    = (const float*)d_in[9];
    const float* bk    = (const float*)d_in[10];
    const float* Wv    = (const float*)d_in[11];
    const float* bv    = (const float*)d_in[12];
    const float* Wo    = (const float*)d_in[13];
    const float* bo    = (const float*)d_in[14];
    float* out = (float*)d_out;

    prep_gemm<<<dim3(6, 8, 15), 256>>>(q_in, k_in, v_in, Wq, bq, Wk, bk, Wv, bv);
    vsum_kernel<<<BB*NHH, DD>>>();
    attn_sparse<<<BB*(SS-3), 256>>>(graph, ek, ev, eq);
    attn_dense<<<BB*3, 256>>>(graph, ek, ev, eq);
    out_gemm<<<dim3(17, 8), 256>>>(Wo, bo, out);
}

// round 4
// speedup vs baseline: 1.0069x; 1.0069x over previous
#include <cuda_runtime.h>
#include <math.h>

// Problem constants
#define BB 2
#define SS 513
#define HH 512
#define NHH 8
#define DD 64
#define SCALE 0.125f   // 1/sqrt(64)

// Scratch (device globals: no allocation allowed)
__device__ float g_Q[BB*SS*HH];
__device__ float g_K[BB*SS*HH];
__device__ float g_V[BB*SS*HH];
__device__ float g_X[BB*SS*HH];
__device__ float g_Vsum[BB*NHH*DD];

// Token index for the i-th row of mask-group f (within one batch).
// f=0,1,2 -> positions 0,1,2 of each 9-long statement (57 each)
// f=3 -> positions 3,5,7 (171); f=4 -> positions 4,6,8 (171)
__device__ __forceinline__ int row_to_token(int f, int i) {
    if (f < 3) return 9*i + f;
    int s = i / 3, j = i % 3;
    return 9*s + ((f == 3) ? (3 + 2*j) : (4 + 2*j));
}

// ---------------------------------------------------------------------------
// Kernel 1: grouped projection GEMM.
// For each (tensor in {q,k,v}, f in 0..4): Y[rows_f] = X[rows_f] @ W_f^T + sum_f b_f
// blockIdx.z = tensor*5 + f; 64x64 tile, BK=16, 256 threads, 4x4 per thread.
// ---------------------------------------------------------------------------
__global__ void prep_gemm(const float* __restrict__ xq, const float* __restrict__ xk,
                          const float* __restrict__ xv,
                          const float* __restrict__ Wq, const float* __restrict__ bq,
                          const float* __restrict__ Wk, const float* __restrict__ bk,
                          const float* __restrict__ Wv, const float* __restrict__ bv) {
    const int g = blockIdx.z;
    const int tensor = g / 5, f = g % 5;
    const int rpb = (f < 3) ? 57 : 171;       // rows per batch in this group
    const int M = 2 * rpb;
    const int m0 = blockIdx.x * 64;
    if (m0 >= M) return;
    const int n0 = blockIdx.y * 64;

    const float* X    = (tensor == 0) ? xq : (tensor == 1) ? xk : xv;
    const float* W    = ((tensor == 0) ? Wq : (tensor == 1) ? Wk : Wv) + f*HH*HH;
    const float* bias = (tensor == 0) ? bq : (tensor == 1) ? bk : bv;
    float* Y          = (tensor == 0) ? g_Q : (tensor == 1) ? g_K : g_V;

    __shared__ float As[64][17];
    __shared__ float Bs[16][68];
    __shared__ int rowoff[64];

    const int tid = threadIdx.x;
    if (tid < 64) {
        int r = m0 + tid;
        if (r < M) {
            int b = r / rpb, i = r % rpb;
            rowoff[tid] = (b*SS + row_to_token(f, i)) * HH;
        } else rowoff[tid] = -1;
    }
    __syncthreads();

    float acc[4][4] = {};
    const int tr = (tid / 16) * 4;
    const int tc = (tid % 16) * 4;

    for (int kk = 0; kk < HH; kk += 16) {
        #pragma unroll
        for (int j = 0; j < 4; j++) {
            int idx = tid*4 + j;
            int r = idx >> 4, c = idx & 15;
            int off = rowoff[r];
            As[r][c] = (off >= 0) ? X[off + kk + c] : 0.f;
        }
        #pragma unroll
        for (int j = 0; j < 4; j++) {
            int idx = tid + j*256;
            int n = idx >> 4, c = idx & 15;
            Bs[c][n] = W[(n0 + n)*HH + kk + c];
        }
        __syncthreads();
        #pragma unroll
        for (int p = 0; p < 16; p++) {
            float a0 = As[tr+0][p], a1 = As[tr+1][p], a2 = As[tr+2][p], a3 = As[tr+3][p];
            float b0 = Bs[p][tc+0], b1 = Bs[p][tc+1], b2 = Bs[p][tc+2], b3 = Bs[p][tc+3];
            acc[0][0] += a0*b0; acc[0][1] += a0*b1; acc[0][2] += a0*b2; acc[0][3] += a0*b3;
            acc[1][0] += a1*b0; acc[1][1] += a1*b1; acc[1][2] += a1*b2; acc[1][3] += a1*b3;
            acc[2][0] += a2*b0; acc[2][1] += a2*b1; acc[2][2] += a2*b2; acc[2][3] += a2*b3;
            acc[3][0] += a3*b0; acc[3][1] += a3*b1; acc[3][2] += a3*b2; acc[3][3] += a3*b3;
        }
        __syncthreads();
    }

    float bsum[4];
    #pragma unroll
    for (int j = 0; j < 4; j++) {
        int n = n0 + tc + j;
        bsum[j] = bias[n] + bias[HH+n] + bias[2*HH+n] + bias[3*HH+n] + bias[4*HH+n];
    }
    #pragma unroll
    for (int i = 0; i < 4; i++) {
        int off = rowoff[tr + i];
        if (off < 0) continue;
        #pragma unroll
        for (int j = 0; j < 4; j++)
            Y[off + n0 + tc + j] = acc[i][j] + bsum[j];
    }
}

// ---------------------------------------------------------------------------
// Kernel 2: per-(b,head) column sums of V  (needed by the fully-masked path)
// ---------------------------------------------------------------------------
__global__ void vsum_kernel() {
    const int b = blockIdx.x / NHH, h = blockIdx.x % NHH;
    const int d = threadIdx.x;
    float a = 0.f;
    for (int k = 0; k < SS; k++) a += g_V[(b*SS + k)*HH + h*DD + d];
    g_Vsum[(b*NHH + h)*DD + d] = a;
}

// ---------------------------------------------------------------------------
// Kernel 3: sparse attention rows (q >= 3): at most 5 kept columns.
// score(q,k,h) = (q_h + eq[k,q]) . (k_h + ek[q,k])   [exact factorization]
// One block per (b,q); 8 warps = 8 heads; lane handles 2 of 64 dims.
// Fully-masked rows reproduce reference softmax(-1e5*ones) = uniform 1/S.
// ---------------------------------------------------------------------------
__global__ void attn_sparse(const int* __restrict__ graph,
                            const float* __restrict__ EK,
                            const float* __restrict__ EV,
                            const float* __restrict__ EQ) {
    const int idx = blockIdx.x;
    const int b = idx / (SS - 3);
    const int q = 3 + idx % (SS - 3);
    const int g2 = 3 + ((q - 3) >> 1) * 2;   // kept pair start
    const int tid = threadIdx.x;

    __shared__ float s_eq[5][64], s_ek[5][64], s_ev[5][64];
    __shared__ int s_g[5];
    __shared__ float s_red[4][64];

    if (tid < 5) {
        int k = (tid < 3) ? tid : g2 + tid - 3;
        s_g[tid] = (graph[(b*SS + q)*SS + k] != 0);
    }
    for (int i = tid; i < 5*64; i += 256) {
        int j = i >> 6, d = i & 63;
        int k = (j < 3) ? j : g2 + j - 3;
        s_eq[j][d] = EQ[((b*SS + k)*SS + q)*DD + d];
        s_ek[j][d] = EK[((b*SS + q)*SS + k)*DD + d];
        s_ev[j][d] = EV[((b*SS + q)*SS + k)*DD + d];
    }
    __syncthreads();

    const int any = s_g[0] | s_g[1] | s_g[2] | s_g[3] | s_g[4];
    const int h = tid >> 5, lane = tid & 31;
    const int d2 = lane * 2;
    const int obase = (b*SS + q)*HH + h*DD + d2;

    if (any) {
        float2 qh = *(const float2*)(g_Q + obase);
        float sc[5];
        #pragma unroll
        for (int j = 0; j < 5; j++) {
            int k = (j < 3) ? j : g2 + j - 3;
            float2 kv = *(const float2*)(g_K + (b*SS + k)*HH + h*DD + d2);
            float s = (qh.x + s_eq[j][d2  ]) * (kv.x + s_ek[j][d2  ])
                    + (qh.y + s_eq[j][d2+1]) * (kv.y + s_ek[j][d2+1]);
            #pragma unroll
            for (int o = 16; o; o >>= 1) s += __shfl_xor_sync(0xffffffffu, s, o);
            sc[j] = s * SCALE;
        }
        float mx = -1e30f;
        #pragma unroll
        for (int j = 0; j < 5; j++) if (s_g[j]) mx = fmaxf(mx, sc[j]);
        float w[5]; float den = 0.f;
        #pragma unroll
        for (int j = 0; j < 5; j++) { w[j] = s_g[j] ? expf(sc[j] - mx) : 0.f; den += w[j]; }
        const float inv = 1.f / den;
        float ax = 0.f, ay = 0.f;
        #pragma unroll
        for (int j = 0; j < 5; j++) {
            float wj = w[j] * inv;
            int k = (j < 3) ? j : g2 + j - 3;
            float2 vv = *(const float2*)(g_V + (b*SS + k)*HH + h*DD + d2);
            ax += wj * (vv.x + s_ev[j][d2  ]);
            ay += wj * (vv.y + s_ev[j][d2+1]);
        }
        g_X[obase] = ax; g_X[obase + 1] = ay;
    } else {
        // reference: softmax of all -100000 -> uniform 1/S over ALL columns
        const int grp = tid >> 6, dd = tid & 63;
        const float* evrow = EV + (b*SS + q)*SS*DD;
        float a = 0.f;
        for (int k = grp; k < SS; k += 4) a += evrow[k*DD + dd];
        s_red[grp][dd] = a;
        __syncthreads();
        float e0 = s_red[0][d2  ] + s_red[1][d2  ] + s_red[2][d2  ] + s_red[3][d2  ];
        float e1 = s_red[0][d2+1] + s_red[1][d2+1] + s_red[2][d2+1] + s_red[3][d2+1];
        float v0 = g_Vsum[(b*NHH + h)*DD + d2];
        float v1 = g_Vsum[(b*NHH + h)*DD + d2 + 1];
        const float u = 1.f / (float)SS;
        g_X[obase]     = (v0 + e0) * u;
        g_X[obase + 1] = (v1 + e1) * u;
    }
}

// ---------------------------------------------------------------------------
// Kernel 4: dense attention rows (q in {0,1,2}): full 513-column softmax,
// masked only by graph. One block per (b,q); scores staged in smem.
// ---------------------------------------------------------------------------
__global__ void attn_dense(const int* __restrict__ graph,
                           const float* __restrict__ EK,
                           const float* __restrict__ EV,
                           const float* __restrict__ EQ) {
    const int b = blockIdx.x / 3;
    const int q = blockIdx.x % 3;
    const int tid = threadIdx.x;
    const int w = tid >> 5, lane = tid & 31, d2 = lane * 2;

    __shared__ float s_q[HH];
    __shared__ float s_s[NHH][SS + 3];
    __shared__ int s_m[SS];

    for (int i = tid; i < HH; i += 256) s_q[i] = g_Q[(b*SS + q)*HH + i];
    for (int k = tid; k < SS; k += 256) s_m[k] = (graph[(b*SS + q)*SS + k] != 0);
    __syncthreads();

    // scores: warp w handles columns k = w, w+8, ...
    for (int k = w; k < SS; k += 8) {
        float eqx = EQ[((b*SS + k)*SS + q)*DD + d2];
        float eqy = EQ[((b*SS + k)*SS + q)*DD + d2 + 1];
        float ekx = EK[((b*SS + q)*SS + k)*DD + d2];
        float eky = EK[((b*SS + q)*SS + k)*DD + d2 + 1];
        #pragma unroll
        for (int h = 0; h < NHH; h++) {
            float2 kv = *(const float2*)(g_K + (b*SS + k)*HH + h*DD + d2);
            float s = (s_q[h*DD + d2] + eqx) * (kv.x + ekx)
                    + (s_q[h*DD + d2 + 1] + eqy) * (kv.y + eky);
            #pragma unroll
            for (int o = 16; o; o >>= 1) s += __shfl_xor_sync(0xffffffffu, s, o);
            if (lane == 0) s_s[h][k] = s * SCALE;
        }
    }
    __syncthreads();

    // masked softmax, warp w = head w
    {
        const int h = w;
        float mx = -1e30f;
        for (int k = lane; k < SS; k += 32) if (s_m[k]) mx = fmaxf(mx, s_s[h][k]);
        #pragma unroll
        for (int o = 16; o; o >>= 1) mx = fmaxf(mx, __shfl_xor_sync(0xffffffffu, mx, o));
        float den = 0.f;
        for (int k = lane; k < SS; k += 32) {
            float e = s_m[k] ? expf(s_s[h][k] - mx) : 0.f;
            s_s[h][k] = e; den += e;
        }
        #pragma unroll
        for (int o = 16; o; o >>= 1) den += __shfl_xor_sync(0xffffffffu, den, o);
        if (den > 0.f) {
            float inv = 1.f / den;
            for (int k = lane; k < SS; k += 32) s_s[h][k] *= inv;
        } else {
            float u = 1.f / (float)SS;       // fully masked -> uniform over all
            for (int k = lane; k < SS; k += 32) s_s[h][k] = u;
        }
    }
    __syncthreads();

    // weighted sum of (v + edge_value)
    {
        const int h = w;
        float ax = 0.f, ay = 0.f;
        for (int k = 0; k < SS; k++) {
            float pk = s_s[h][k];
            if (pk != 0.f) {
                float2 vv = *(const float2*)(g_V + (b*SS + k)*HH + h*DD + d2);
                float evx = EV[((b*SS + q)*SS + k)*DD + d2];
                float evy = EV[((b*SS + q)*SS + k)*DD + d2 + 1];
                ax += pk * (vv.x + evx);
                ay += pk * (vv.y + evy);
            }
        }
        int ob = (b*SS + q)*HH + h*DD + d2;
        g_X[ob] = ax; g_X[ob + 1] = ay;
    }
}

// ---------------------------------------------------------------------------
// Kernel 5: output projection  out = X @ Wo^T + bo   (M=1026, N=K=512)
// ---------------------------------------------------------------------------
__global__ void out_gemm(const float* __restrict__ Wo, const float* __restrict__ bo,
                         float* __restrict__ out) {
    const int M = BB * SS;
    const int m0 = blockIdx.x * 64;
    const int n0 = blockIdx.y * 64;

    __shared__ float As[64][17];
    __shared__ float Bs[16][68];

    const int tid = threadIdx.x;
    float acc[4][4] = {};
    const int tr = (tid / 16) * 4;
    const int tc = (tid % 16) * 4;

    for (int kk = 0; kk < HH; kk += 16) {
        #pragma unroll
        for (int j = 0; j < 4; j++) {
            int idx = tid*4 + j;
            int r = idx >> 4, c = idx & 15;
            int row = m0 + r;
            As[r][c] = (row < M) ? g_X[row*HH + kk + c] : 0.f;
        }
        #pragma unroll
        for (int j = 0; j < 4; j++) {
            int idx = tid + j*256;
            int n = idx >> 4, c = idx & 15;
            Bs[c][n] = Wo[(n0 + n)*HH + kk + c];
        }
        __syncthreads();
        #pragma unroll
        for (int p = 0; p < 16; p++) {
            float a0 = As[tr+0][p], a1 = As[tr+1][p], a2 = As[tr+2][p], a3 = As[tr+3][p];
            float b0 = Bs[p][tc+0], b1 = Bs[p][tc+1], b2 = Bs[p][tc+2], b3 = Bs[p][tc+3];
            acc[0][0] += a0*b0; acc[0][1] += a0*b1; acc[0][2] += a0*b2; acc[0][3] += a0*b3;
            acc[1][0] += a1*b0; acc[1][1] += a1*b1; acc[1][2] += a1*b2; acc[1][3] += a1*b3;
            acc[2][0] += a2*b0; acc[2][1] += a2*b1; acc[2][2] += a2*b2; acc[2][3] += a2*b3;
            acc[3][0] += a3*b0; acc[3][1] += a3*b1; acc[3][2] += a3*b2; acc[3][3] += a3*b3;
        }
        __syncthreads();
    }
    #pragma unroll
    for (int i = 0; i < 4; i++) {
        int row = m0 + tr + i;
        if (row >= M) continue;
        #pragma unroll
        for (int j = 0; j < 4; j++)
            out[row*HH + n0 + tc + j] = acc[i][j] + bo[n0 + tc + j];
    }
}

// ---------------------------------------------------------------------------
extern "C" void kernel_launch(void* const* d_in, const int* in_sizes, int n_in,
                              void* d_out, int out_size) {
    (void)in_sizes; (void)n_in; (void)out_size;
    const float* q_in  = (const float*)d_in[0];
    const float* k_in  = (const float*)d_in[1];
    const float* v_in  = (const float*)d_in[2];
    const int*   graph = (const int*)  d_in[3];   // bool -> 32-bit nonzero test (i32 or f32 safe)
    const float* ek    = (const float*)d_in[4];
    const float* ev    = (const float*)d_in[5];
    const float* eq    = (const float*)d_in[6];
    const float* Wq    = (const float*)d_in[7];
    const float* bq    = (const float*)d_in[8];
    const float* Wk    = (const float*)d_in[9];
    const float* bk    = (const float*)d_in[10];
    const float* Wv    = (const float*)d_in[11];
    const float* bv    = (const float*)d_in[12];
    const float* Wo    = (const float*)d_in[13];
    const float* bo    = (const float*)d_in[14];
    float* out = (float*)d_out;

    prep_gemm<<<dim3(6, 8, 15), 256>>>(q_in, k_in, v_in, Wq, bq, Wk, bk, Wv, bv);
    vsum_kernel<<<BB*NHH, DD>>>();
    attn_sparse<<<BB*(SS-3), 256>>>(graph, ek, ev, eq);
    attn_dense<<<BB*3, 256>>>(graph, ek, ev, eq);
    out_gemm<<<dim3(17, 8), 256>>>(Wo, bo, out);
}